// round 5
// baseline (speedup 1.0000x reference)
#include <cuda_runtime.h>

#define T_LEN 1024
#define D_IN  1024
#define H_HID 512
#define G4    2048
#define BATCH 32
#define ROWS  32768          // T*B
#define NCOL  4096           // 2 dirs * 4H

// ---------------- device scratch ----------------
__device__ float g_xA[(size_t)D_IN * ROWS];     // x transposed: [k][row], row = t*32+b
__device__ float g_xg[(size_t)NCOL * ROWS];     // input projections, col-major: [col][row]
__device__ float g_hbuf[2][2][H_HID * BATCH];   // [buf][dir][j*32+b]
__device__ float g_part[128][T_LEN][BATCH];     // per-block logit partials
__device__ unsigned g_flag[2][64];              // per-block step flags

// ---------------- f32x2 helpers ----------------
__device__ __forceinline__ unsigned long long splat2(float v) {
    unsigned long long r; unsigned u = __float_as_uint(v);
    asm("mov.b64 %0, {%1, %1};" : "=l"(r) : "r"(u));
    return r;
}
#define FMA2(acc, xv, wv) \
    asm("fma.rn.f32x2 %0, %1, %2, %0;" : "+l"(acc) : "l"(xv), "l"(wv))
__device__ __forceinline__ void unpack2(unsigned long long a, float& lo, float& hi) {
    unsigned l, h;
    asm("mov.b64 {%0, %1}, %2;" : "=r"(l), "=r"(h) : "l"(a));
    lo = __uint_as_float(l); hi = __uint_as_float(h);
}

// ---------------- kernel 1: zero recurrent state + flags ----------------
__global__ void zero_state_kernel() {
    int i = blockIdx.x * blockDim.x + threadIdx.x;
    ((float*)g_hbuf)[i] = 0.0f;       // 65536 threads exactly
    if (i < 128) ((unsigned*)g_flag)[i] = 0u;
}

// ---------------- kernel 2: transpose x[B][T][D] -> xA[k][t*32+b] ----------------
__global__ void transpose_x_kernel(const float* __restrict__ x) {
    __shared__ float tile[32][33];
    int t = blockIdx.x, k0 = blockIdx.y * 32, tid = threadIdx.x;
    int kk = tid & 31, r = tid >> 5;
#pragma unroll
    for (int i = 0; i < 4; ++i) {
        int b = r + i * 8;
        tile[kk][b] = x[((size_t)b * T_LEN + t) * D_IN + k0 + kk];
    }
    __syncthreads();
    int b2 = tid & 31, kr = tid >> 5;
#pragma unroll
    for (int i = 0; i < 4; ++i) {
        int kk2 = kr + i * 8;
        g_xA[(size_t)(k0 + kk2) * ROWS + t * 32 + b2] = tile[kk2][b2];
    }
}

// ---------------- kernel 3: xg = A @ [Wx_f | Wx_b]  (fp32 FFMA2 GEMM) ----------------
__global__ void __launch_bounds__(256, 2)
gemm_kernel(const float* __restrict__ Wx_f, const float* __restrict__ Wx_b) {
    extern __shared__ float sm[];
    float* xs  = sm;          // [2][32*128]  A tile  [kk][row]
    float* ws2 = sm + 8192;   // [2][32*128]  W tile, duplicated pairs [kk][col*2]

    const int tid = threadIdx.x;
    const int cb = blockIdx.x, rb = blockIdx.y;
    const int r = tid & 15, cg = tid >> 4;

    unsigned long long acc[4][4];
#pragma unroll
    for (int p = 0; p < 4; ++p)
#pragma unroll
        for (int c = 0; c < 4; ++c) acc[p][c] = 0ull;

    float4 ar[4], wr[2];

    auto load_regs = [&](int ti) {
        int k0 = ti * 32;
#pragma unroll
        for (int i = 0; i < 4; ++i) {
            int f = tid + i * 256;
            int kk = f >> 5, rc = (f & 31) * 4;
            ar[i] = *(const float4*)(g_xA + (size_t)(k0 + kk) * ROWS + rb * 128 + rc);
        }
#pragma unroll
        for (int i = 0; i < 2; ++i) {
            int f = tid + i * 256;
            int kk = f >> 4, cc = (f & 15) * 4;
            int gcol = cb * 64 + cc;
            const float* src = (gcol < G4)
                ? (Wx_f + (size_t)(k0 + kk) * G4 + gcol)
                : (Wx_b + (size_t)(k0 + kk) * G4 + (gcol - G4));
            wr[i] = *(const float4*)src;
        }
    };
    auto store_smem = [&](int buf) {
        float* xb = xs + buf * 4096;
        float* wb = ws2 + buf * 4096;
#pragma unroll
        for (int i = 0; i < 4; ++i) {
            int f = tid + i * 256;
            int kk = f >> 5, rc = (f & 31) * 4;
            *(float4*)(xb + kk * 128 + rc) = ar[i];
        }
#pragma unroll
        for (int i = 0; i < 2; ++i) {
            int f = tid + i * 256;
            int kk = f >> 4, cc = (f & 15) * 4;
            float4 w = wr[i];
            *(float4*)(wb + kk * 128 + cc * 2)     = make_float4(w.x, w.x, w.y, w.y);
            *(float4*)(wb + kk * 128 + cc * 2 + 4) = make_float4(w.z, w.z, w.w, w.w);
        }
    };

    load_regs(0);
    store_smem(0);
    __syncthreads();

    for (int ti = 0; ti < 32; ++ti) {
        if (ti + 1 < 32) load_regs(ti + 1);
        const float* xb = xs + (ti & 1) * 4096 + r * 8;
        const float* wb = ws2 + (ti & 1) * 4096 + cg * 8;
#pragma unroll 4
        for (int kk = 0; kk < 32; ++kk) {
            ulonglong2 xq0 = *(const ulonglong2*)(xb);
            ulonglong2 xq1 = *(const ulonglong2*)(xb + 4);
            ulonglong2 wq0 = *(const ulonglong2*)(wb);
            ulonglong2 wq1 = *(const ulonglong2*)(wb + 4);
            FMA2(acc[0][0], xq0.x, wq0.x); FMA2(acc[0][1], xq0.x, wq0.y);
            FMA2(acc[0][2], xq0.x, wq1.x); FMA2(acc[0][3], xq0.x, wq1.y);
            FMA2(acc[1][0], xq0.y, wq0.x); FMA2(acc[1][1], xq0.y, wq0.y);
            FMA2(acc[1][2], xq0.y, wq1.x); FMA2(acc[1][3], xq0.y, wq1.y);
            FMA2(acc[2][0], xq1.x, wq0.x); FMA2(acc[2][1], xq1.x, wq0.y);
            FMA2(acc[2][2], xq1.x, wq1.x); FMA2(acc[2][3], xq1.x, wq1.y);
            FMA2(acc[3][0], xq1.y, wq0.x); FMA2(acc[3][1], xq1.y, wq0.y);
            FMA2(acc[3][2], xq1.y, wq1.x); FMA2(acc[3][3], xq1.y, wq1.y);
            xb += 128; wb += 128;
        }
        if (ti + 1 < 32) store_smem((ti + 1) & 1);
        __syncthreads();
    }

#pragma unroll
    for (int c = 0; c < 4; ++c) {
        float v[8];
#pragma unroll
        for (int p = 0; p < 4; ++p) unpack2(acc[p][c], v[2 * p], v[2 * p + 1]);
        size_t col = (size_t)cb * 64 + cg * 4 + c;
        float* d = g_xg + col * ROWS + rb * 128 + r * 8;
        *(float4*)d       = make_float4(v[0], v[1], v[2], v[3]);
        *(float4*)(d + 4) = make_float4(v[4], v[5], v[6], v[7]);
    }
}

// ---------------- kernel 4: persistent recurrent phase ----------------
// 128 blocks, 512 threads. dir = blk>>6, 8 hidden units per block (j0=(blk&63)*8)
// = 32 gate columns. 8-way k-split (64 k's per slice).
__global__ void __launch_bounds__(512, 1)
lstm_kernel(const float* __restrict__ Wh_f, const float* __restrict__ Wh_b,
            const float* __restrict__ b_f,  const float* __restrict__ b_b,
            const float* __restrict__ Wfc)
{
    extern __shared__ float sm[];
    float* hs   = sm;             // 16384 : h(t-1) [k][b]
    float* ws   = sm + 16384;     // 16384 : Wh slice [kk][cc]
    float* part = sm + 32768;     // 8192  : k-split partials [slice][cc][b]
    float* psum = sm + 40960;     // 256   : logit partial reduction

    const int tid = threadIdx.x;
    const int blk = blockIdx.x;
    const int dir = blk >> 6;
    const int j0  = (blk & 63) * 8;

    // k-loop mapping: 8 slices of 64 k's
    const int slice = tid >> 6;          // 0..7
    const int q     = tid & 63;
    const int cp    = q & 15;            // column pair 2cp, 2cp+1
    const int bo    = q >> 4;            // batch octet

    // cell mapping (threads < 256)
    const int u = tid >> 5;              // hidden unit 0..7 (for tid<256)
    const int b = tid & 31;

    const float* Wh   = dir ? Wh_b : Wh_f;
    const float* bias = dir ? b_b  : b_f;

    // load Wh slice once: ws[kk*32 + g*8+uu] = Wh[kk][g*512 + j0 + uu]
    for (int e = tid; e < 512 * 32; e += 512) {
        int kk = e >> 5, cc = e & 31;
        int g = cc >> 3, uu = cc & 7;
        ws[e] = Wh[(size_t)kk * G4 + g * 512 + j0 + uu];
    }

    float biasr[4] = {0, 0, 0, 0};
    float wfc = 0.0f;
    if (tid < 256) {
#pragma unroll
        for (int g = 0; g < 4; ++g) biasr[g] = bias[g * 512 + j0 + u];
        wfc = Wfc[dir * H_HID + j0 + u];
    }

    float cstate = 0.0f;
    __syncthreads();

    for (int s = 0; s < T_LEN; ++s) {
        const int t = dir ? (T_LEN - 1 - s) : s;
        const float* hprev = g_hbuf[s & 1][dir];
        float*       hnext = g_hbuf[(s + 1) & 1][dir];

        // wait for all 64 blocks of this dir to have published h(t-1)
        if (s > 0) {
            if (tid < 64) {
                volatile unsigned* f = &g_flag[dir][tid];
                while (*f < (unsigned)s) { }
                __threadfence();
            }
            __syncthreads();
        }

        // stage h(t-1): 64KB, 8 float4 per thread
        {
            const float4* src = (const float4*)hprev;
            float4* dst = (float4*)hs;
#pragma unroll
            for (int i = 0; i < 8; ++i) dst[tid + i * 512] = src[tid + i * 512];
        }
        // prefetch xg (epilogue operands)
        float xgv[4] = {0, 0, 0, 0};
        if (tid < 256) {
#pragma unroll
            for (int g = 0; g < 4; ++g)
                xgv[g] = __ldg(g_xg + (size_t)(dir * G4 + g * 512 + j0 + u) * ROWS + t * 32 + b);
        }
        __syncthreads();

        // k-loop: 64 k's per slice, 8 FMA2 per k
        unsigned long long a0[4], a1[4];
#pragma unroll
        for (int p = 0; p < 4; ++p) { a0[p] = 0ull; a1[p] = 0ull; }
        {
            const float* hp = hs + slice * 64 * 32 + bo * 8;
            const float* wp = ws + slice * 64 * 32 + 2 * cp;
#pragma unroll 4
            for (int kk = 0; kk < 64; ++kk) {
                ulonglong2 hq0 = *(const ulonglong2*)hp;
                ulonglong2 hq1 = *(const ulonglong2*)(hp + 4);
                unsigned long long w0 = splat2(wp[0]);
                unsigned long long w1 = splat2(wp[1]);
                FMA2(a0[0], hq0.x, w0); FMA2(a0[1], hq0.y, w0);
                FMA2(a0[2], hq1.x, w0); FMA2(a0[3], hq1.y, w0);
                FMA2(a1[0], hq0.x, w1); FMA2(a1[1], hq0.y, w1);
                FMA2(a1[2], hq1.x, w1); FMA2(a1[3], hq1.y, w1);
                hp += 32; wp += 32;
            }
        }
        // write k-split partials
        {
            float* p0 = part + slice * 1024 + (2 * cp) * 32 + bo * 8;
            float* p1 = p0 + 32;
            *(ulonglong2*)p0       = make_ulonglong2(a0[0], a0[1]);
            *(ulonglong2*)(p0 + 4) = make_ulonglong2(a0[2], a0[3]);
            *(ulonglong2*)p1       = make_ulonglong2(a1[0], a1[1]);
            *(ulonglong2*)(p1 + 4) = make_ulonglong2(a1[2], a1[3]);
        }
        __syncthreads();

        // epilogue: threads < 256 compute cell update for (u, b)
        if (tid < 256) {
            float gate[4];
#pragma unroll
            for (int g = 0; g < 4; ++g) {
                int cc = g * 8 + u;
                float sum = xgv[g] + biasr[g];
#pragma unroll
                for (int sl = 0; sl < 8; ++sl) sum += part[sl * 1024 + cc * 32 + b];
                gate[g] = sum;
            }
            float iv = 1.0f / (1.0f + __expf(-gate[0]));
            float fv = 1.0f / (1.0f + __expf(-gate[1]));
            float gv = tanhf(gate[2]);
            float ov = 1.0f / (1.0f + __expf(-gate[3]));
            cstate = fv * cstate + iv * gv;
            float hv = ov * tanhf(cstate);
            hnext[(j0 + u) * 32 + b] = hv;
            psum[tid] = hv * wfc;
        }
        __syncthreads();
        if (tid < 32) {
            float tot = 0.0f;
#pragma unroll
            for (int uu = 0; uu < 8; ++uu) tot += psum[tid + uu * 32];
            g_part[blk][t][tid] = tot;
        }
        if (tid == 0 && s + 1 < T_LEN) {
            __threadfence();
            g_flag[dir][blk & 63] = (unsigned)(s + 1);
        }
    }
}

// ---------------- kernel 5: reduce partials + sigmoid ----------------
__global__ void finalize_kernel(const float* __restrict__ b_fc, float* __restrict__ out) {
    int g = blockIdx.x * blockDim.x + threadIdx.x;
    if (g >= T_LEN * BATCH) return;
    int t = g >> 5, b = g & 31;
    float acc = b_fc[0];
    const float* p = &g_part[0][t][b];
#pragma unroll 8
    for (int blk = 0; blk < 128; ++blk)
        acc += p[(size_t)blk * T_LEN * BATCH];
    out[(size_t)b * T_LEN + t] = 1.0f / (1.0f + __expf(-acc));
}

// ---------------- launcher ----------------
extern "C" void kernel_launch(void* const* d_in, const int* in_sizes, int n_in,
                              void* d_out, int out_size) {
    const float* x    = (const float*)d_in[0];
    const float* Wx_f = (const float*)d_in[1];
    const float* Wh_f = (const float*)d_in[2];
    const float* b_f  = (const float*)d_in[3];
    const float* Wx_b = (const float*)d_in[4];
    const float* Wh_b = (const float*)d_in[5];
    const float* b_b  = (const float*)d_in[6];
    const float* Wfc  = (const float*)d_in[7];
    const float* bfc  = (const float*)d_in[8];
    float* out = (float*)d_out;
    (void)in_sizes; (void)n_in; (void)out_size;

    cudaFuncSetAttribute(gemm_kernel, cudaFuncAttributeMaxDynamicSharedMemorySize, 65536);
    cudaFuncSetAttribute(lstm_kernel, cudaFuncAttributeMaxDynamicSharedMemorySize, 165888);

    zero_state_kernel<<<256, 256>>>();
    transpose_x_kernel<<<dim3(T_LEN, D_IN / 32), 256>>>(x);
    gemm_kernel<<<dim3(64, 256), 256, 65536>>>(Wx_f, Wx_b);
    lstm_kernel<<<128, 512, 165888>>>(Wh_f, Wh_b, b_f, b_b, Wfc);
    finalize_kernel<<<128, 256>>>(bfc, out);
}

// round 6
// speedup vs baseline: 1.0204x; 1.0204x over previous
#include <cuda_runtime.h>

#define T_LEN 1024
#define D_IN  1024
#define H_HID 512
#define G4    2048
#define BATCH 32
#define ROWS  32768          // T*B
#define NCOL  4096           // 2 dirs * 4H

// ---------------- device scratch ----------------
__device__ float g_xA[(size_t)D_IN * ROWS];     // x transposed: [k][row], row = t*32+b
__device__ float g_xg[(size_t)NCOL * ROWS];     // input projections, col-major: [col][row]
__device__ float g_hbuf[2][2][H_HID * BATCH];   // [buf][dir][j*32+b]
__device__ float g_part[128][T_LEN][BATCH];     // per-block logit partials
__device__ unsigned g_flag[2][64];              // per-block completed-step counters

// ---------------- f32x2 helpers ----------------
__device__ __forceinline__ unsigned long long splat2(float v) {
    unsigned long long r; unsigned u = __float_as_uint(v);
    asm("mov.b64 %0, {%1, %1};" : "=l"(r) : "r"(u));
    return r;
}
#define FMA2(acc, xv, wv) \
    asm("fma.rn.f32x2 %0, %1, %2, %0;" : "+l"(acc) : "l"(xv), "l"(wv))
__device__ __forceinline__ void unpack2(unsigned long long a, float& lo, float& hi) {
    unsigned l, h;
    asm("mov.b64 {%0, %1}, %2;" : "=r"(l), "=r"(h) : "l"(a));
    lo = __uint_as_float(l); hi = __uint_as_float(h);
}

// ---------------- kernel 1: zero recurrent state + flags ----------------
__global__ void zero_state_kernel() {
    int i = blockIdx.x * blockDim.x + threadIdx.x;
    ((float*)g_hbuf)[i] = 0.0f;       // 65536 threads exactly
    if (i < 128) ((unsigned*)g_flag)[i] = 0u;
}

// ---------------- kernel 2: transpose x[B][T][D] -> xA[k][t*32+b] ----------------
__global__ void transpose_x_kernel(const float* __restrict__ x) {
    __shared__ float tile[32][33];
    int t = blockIdx.x, k0 = blockIdx.y * 32, tid = threadIdx.x;
    int kk = tid & 31, r = tid >> 5;
#pragma unroll
    for (int i = 0; i < 4; ++i) {
        int b = r + i * 8;
        tile[kk][b] = x[((size_t)b * T_LEN + t) * D_IN + k0 + kk];
    }
    __syncthreads();
    int b2 = tid & 31, kr = tid >> 5;
#pragma unroll
    for (int i = 0; i < 4; ++i) {
        int kk2 = kr + i * 8;
        g_xA[(size_t)(k0 + kk2) * ROWS + t * 32 + b2] = tile[kk2][b2];
    }
}

// ---------------- kernel 3: xg = A @ [Wx_f | Wx_b]  (fp32 FFMA2 GEMM) ----------------
__global__ void __launch_bounds__(256, 2)
gemm_kernel(const float* __restrict__ Wx_f, const float* __restrict__ Wx_b) {
    extern __shared__ float sm[];
    float* xs  = sm;          // [2][32*128]  A tile  [kk][row]
    float* ws2 = sm + 8192;   // [2][32*128]  W tile, duplicated pairs [kk][col*2]

    const int tid = threadIdx.x;
    const int cb = blockIdx.x, rb = blockIdx.y;
    const int r = tid & 15, cg = tid >> 4;

    unsigned long long acc[4][4];
#pragma unroll
    for (int p = 0; p < 4; ++p)
#pragma unroll
        for (int c = 0; c < 4; ++c) acc[p][c] = 0ull;

    float4 ar[4], wr[2];

    auto load_regs = [&](int ti) {
        int k0 = ti * 32;
#pragma unroll
        for (int i = 0; i < 4; ++i) {
            int f = tid + i * 256;
            int kk = f >> 5, rc = (f & 31) * 4;
            ar[i] = *(const float4*)(g_xA + (size_t)(k0 + kk) * ROWS + rb * 128 + rc);
        }
#pragma unroll
        for (int i = 0; i < 2; ++i) {
            int f = tid + i * 256;
            int kk = f >> 4, cc = (f & 15) * 4;
            int gcol = cb * 64 + cc;
            const float* src = (gcol < G4)
                ? (Wx_f + (size_t)(k0 + kk) * G4 + gcol)
                : (Wx_b + (size_t)(k0 + kk) * G4 + (gcol - G4));
            wr[i] = *(const float4*)src;
        }
    };
    auto store_smem = [&](int buf) {
        float* xb = xs + buf * 4096;
        float* wb = ws2 + buf * 4096;
#pragma unroll
        for (int i = 0; i < 4; ++i) {
            int f = tid + i * 256;
            int kk = f >> 5, rc = (f & 31) * 4;
            *(float4*)(xb + kk * 128 + rc) = ar[i];
        }
#pragma unroll
        for (int i = 0; i < 2; ++i) {
            int f = tid + i * 256;
            int kk = f >> 4, cc = (f & 15) * 4;
            float4 w = wr[i];
            *(float4*)(wb + kk * 128 + cc * 2)     = make_float4(w.x, w.x, w.y, w.y);
            *(float4*)(wb + kk * 128 + cc * 2 + 4) = make_float4(w.z, w.z, w.w, w.w);
        }
    };

    load_regs(0);
    store_smem(0);
    __syncthreads();

    for (int ti = 0; ti < 32; ++ti) {
        if (ti + 1 < 32) load_regs(ti + 1);
        const float* xb = xs + (ti & 1) * 4096 + r * 8;
        const float* wb = ws2 + (ti & 1) * 4096 + cg * 8;
#pragma unroll 4
        for (int kk = 0; kk < 32; ++kk) {
            ulonglong2 xq0 = *(const ulonglong2*)(xb);
            ulonglong2 xq1 = *(const ulonglong2*)(xb + 4);
            ulonglong2 wq0 = *(const ulonglong2*)(wb);
            ulonglong2 wq1 = *(const ulonglong2*)(wb + 4);
            FMA2(acc[0][0], xq0.x, wq0.x); FMA2(acc[0][1], xq0.x, wq0.y);
            FMA2(acc[0][2], xq0.x, wq1.x); FMA2(acc[0][3], xq0.x, wq1.y);
            FMA2(acc[1][0], xq0.y, wq0.x); FMA2(acc[1][1], xq0.y, wq0.y);
            FMA2(acc[1][2], xq0.y, wq1.x); FMA2(acc[1][3], xq0.y, wq1.y);
            FMA2(acc[2][0], xq1.x, wq0.x); FMA2(acc[2][1], xq1.x, wq0.y);
            FMA2(acc[2][2], xq1.x, wq1.x); FMA2(acc[2][3], xq1.x, wq1.y);
            FMA2(acc[3][0], xq1.y, wq0.x); FMA2(acc[3][1], xq1.y, wq0.y);
            FMA2(acc[3][2], xq1.y, wq1.x); FMA2(acc[3][3], xq1.y, wq1.y);
            xb += 128; wb += 128;
        }
        if (ti + 1 < 32) store_smem((ti + 1) & 1);
        __syncthreads();
    }

#pragma unroll
    for (int c = 0; c < 4; ++c) {
        float v[8];
#pragma unroll
        for (int p = 0; p < 4; ++p) unpack2(acc[p][c], v[2 * p], v[2 * p + 1]);
        size_t col = (size_t)cb * 64 + cg * 4 + c;
        float* d = g_xg + col * ROWS + rb * 128 + r * 8;
        *(float4*)d       = make_float4(v[0], v[1], v[2], v[3]);
        *(float4*)(d + 4) = make_float4(v[4], v[5], v[6], v[7]);
    }
}

// ---------------- kernel 4: persistent recurrent phase ----------------
// 128 blocks, 256 threads. dir = blk>>6, 8 hidden units/block (j0=(blk&63)*8)
// = 32 gate columns. 4-way k-split, duplicated weight pairs in smem.
__global__ void __launch_bounds__(256, 1)
lstm_kernel(const float* __restrict__ Wh_f, const float* __restrict__ Wh_b,
            const float* __restrict__ b_f,  const float* __restrict__ b_b,
            const float* __restrict__ Wfc)
{
    extern __shared__ float sm[];
    float* hs   = sm;             // 16384 fl (64KB)  : h(t-1) [k][b]
    float* ws   = sm + 16384;     // 32768 fl (128KB) : Wh dup pairs [k][cp*4]
    float* part = sm + 49152;     // 4096 fl (16KB)   : [slice][cc][b]
    float* psum = sm + 53248;     // 256 fl

    const int tid = threadIdx.x;
    const int blk = blockIdx.x;
    const int dir = blk >> 6;
    const int j0  = (blk & 63) * 8;
    const int lane = tid & 31;

    // k-loop mapping: 4 slices x 64 threads
    const int slice = tid >> 6;          // 0..3  (k range slice*128..+127)
    const int q     = tid & 63;
    const int cp    = q & 15;            // column pair 2cp, 2cp+1
    const int bo    = q >> 4;            // batch octet

    // cell mapping
    const int u = tid >> 5;              // hidden unit 0..7
    const int b = tid & 31;

    const float* Wh   = dir ? Wh_b : Wh_f;
    const float* bias = dir ? b_b  : b_f;

    // load Wh slice once, duplicated pairs: ws[k*64 + p*4] = {w0,w0,w1,w1}
    for (int e = tid; e < 512 * 16; e += 256) {
        int k = e >> 4, p = e & 15;
        int cc0 = 2 * p, cc1 = 2 * p + 1;
        float w0 = Wh[(size_t)k * G4 + (cc0 >> 3) * 512 + j0 + (cc0 & 7)];
        float w1 = Wh[(size_t)k * G4 + (cc1 >> 3) * 512 + j0 + (cc1 & 7)];
        *(float4*)(ws + k * 64 + p * 4) = make_float4(w0, w0, w1, w1);
    }

    float biasr[4];
#pragma unroll
    for (int g = 0; g < 4; ++g) biasr[g] = bias[g * 512 + j0 + u];
    const float wfc = Wfc[dir * H_HID + j0 + u];

    float cstate = 0.0f;
    __syncthreads();

    volatile unsigned* f0 = &g_flag[dir][lane];
    volatile unsigned* f1 = &g_flag[dir][lane + 32];

    for (int s = 0; s < T_LEN; ++s) {
        const int t = dir ? (T_LEN - 1 - s) : s;
        const float* hprev = g_hbuf[s & 1][dir];
        float*       hnext = g_hbuf[(s + 1) & 1][dir];

        // prefetch xg (independent of h)
        float xgv[4];
#pragma unroll
        for (int g = 0; g < 4; ++g)
            xgv[g] = __ldg(g_xg + (size_t)(dir * G4 + g * 512 + j0 + u) * ROWS + t * 32 + b);

        // warp-autonomous wait: every warp polls all 64 flags of its dir
        if (s > 0) {
            bool ok;
            do {
                ok = (*f0 >= (unsigned)s) && (*f1 >= (unsigned)s);
            } while (!__all_sync(0xffffffffu, ok));
            __threadfence();
        }

        // per-slice staging: the 64 threads of a slice stage their 16KB of h
        {
            const float4* src = (const float4*)(hprev + slice * 128 * 32);
            float4* dst = (float4*)(hs + slice * 128 * 32);
#pragma unroll
            for (int i = 0; i < 16; ++i) dst[q + i * 64] = src[q + i * 64];
        }
        asm volatile("bar.sync %0, %1;" :: "r"(slice + 1), "r"(64) : "memory");

        // k-loop: 128 k's per slice; 3 LDS.128 + 8 FMA2 per k
        unsigned long long a0[4], a1[4];
#pragma unroll
        for (int p = 0; p < 4; ++p) { a0[p] = 0ull; a1[p] = 0ull; }
        {
            const float* hp = hs + slice * 128 * 32 + bo * 8;
            const float* wp = ws + slice * 128 * 64 + cp * 4;
#pragma unroll 4
            for (int kk = 0; kk < 128; ++kk) {
                ulonglong2 hq0 = *(const ulonglong2*)hp;
                ulonglong2 hq1 = *(const ulonglong2*)(hp + 4);
                ulonglong2 wq  = *(const ulonglong2*)wp;
                FMA2(a0[0], hq0.x, wq.x); FMA2(a0[1], hq0.y, wq.x);
                FMA2(a0[2], hq1.x, wq.x); FMA2(a0[3], hq1.y, wq.x);
                FMA2(a1[0], hq0.x, wq.y); FMA2(a1[1], hq0.y, wq.y);
                FMA2(a1[2], hq1.x, wq.y); FMA2(a1[3], hq1.y, wq.y);
                hp += 32; wp += 64;
            }
        }
        // write k-split partials
        {
            float* p0 = part + slice * 1024 + (2 * cp) * 32 + bo * 8;
            float* p1 = p0 + 32;
            *(ulonglong2*)p0       = make_ulonglong2(a0[0], a0[1]);
            *(ulonglong2*)(p0 + 4) = make_ulonglong2(a0[2], a0[3]);
            *(ulonglong2*)p1       = make_ulonglong2(a1[0], a1[1]);
            *(ulonglong2*)(p1 + 4) = make_ulonglong2(a1[2], a1[3]);
        }
        __syncthreads();

        // epilogue: thread (u, b) computes cell update
        {
            float gate[4];
#pragma unroll
            for (int g = 0; g < 4; ++g) {
                int cc = g * 8 + u;
                float sum = xgv[g] + biasr[g];
#pragma unroll
                for (int sl = 0; sl < 4; ++sl) sum += part[sl * 1024 + cc * 32 + b];
                gate[g] = sum;
            }
            float iv = 1.0f / (1.0f + __expf(-gate[0]));
            float fv = 1.0f / (1.0f + __expf(-gate[1]));
            float gv = tanhf(gate[2]);
            float ov = 1.0f / (1.0f + __expf(-gate[3]));
            cstate = fv * cstate + iv * gv;
            float hv = ov * tanhf(cstate);
            hnext[(j0 + u) * 32 + b] = hv;
            psum[tid] = hv * wfc;
        }
        __syncthreads();
        // release (overlaps psum reduction)
        if (tid == 64 && s + 1 < T_LEN) {
            __threadfence();
            g_flag[dir][blk & 63] = (unsigned)(s + 1);
        }
        if (tid < 32) {
            float tot = 0.0f;
#pragma unroll
            for (int uu = 0; uu < 8; ++uu) tot += psum[tid + uu * 32];
            g_part[blk][t][tid] = tot;
        }
    }
}

// ---------------- kernel 5: reduce partials + sigmoid ----------------
__global__ void finalize_kernel(const float* __restrict__ b_fc, float* __restrict__ out) {
    int g = blockIdx.x * blockDim.x + threadIdx.x;
    if (g >= T_LEN * BATCH) return;
    int t = g >> 5, b = g & 31;
    float acc = b_fc[0];
    const float* p = &g_part[0][t][b];
#pragma unroll 8
    for (int blk = 0; blk < 128; ++blk)
        acc += p[(size_t)blk * T_LEN * BATCH];
    out[(size_t)b * T_LEN + t] = 1.0f / (1.0f + __expf(-acc));
}

// ---------------- launcher ----------------
extern "C" void kernel_launch(void* const* d_in, const int* in_sizes, int n_in,
                              void* d_out, int out_size) {
    const float* x    = (const float*)d_in[0];
    const float* Wx_f = (const float*)d_in[1];
    const float* Wh_f = (const float*)d_in[2];
    const float* b_f  = (const float*)d_in[3];
    const float* Wx_b = (const float*)d_in[4];
    const float* Wh_b = (const float*)d_in[5];
    const float* b_b  = (const float*)d_in[6];
    const float* Wfc  = (const float*)d_in[7];
    const float* bfc  = (const float*)d_in[8];
    float* out = (float*)d_out;
    (void)in_sizes; (void)n_in; (void)out_size;

    cudaFuncSetAttribute(gemm_kernel, cudaFuncAttributeMaxDynamicSharedMemorySize, 65536);
    cudaFuncSetAttribute(lstm_kernel, cudaFuncAttributeMaxDynamicSharedMemorySize, 214016);

    zero_state_kernel<<<256, 256>>>();
    transpose_x_kernel<<<dim3(T_LEN, D_IN / 32), 256>>>(x);
    gemm_kernel<<<dim3(64, 256), 256, 65536>>>(Wx_f, Wx_b);
    lstm_kernel<<<128, 256, 214016>>>(Wh_f, Wh_b, b_f, b_b, Wfc);
    finalize_kernel<<<128, 256>>>(bfc, out);
}

// round 7
// speedup vs baseline: 1.3575x; 1.3304x over previous
#include <cuda_runtime.h>

#define T_LEN 1024
#define D_IN  1024
#define H_HID 512
#define G4    2048
#define BATCH 32
#define ROWS  32768          // T*B
#define NCOL  4096           // 2 dirs * 4H

// ---------------- device scratch ----------------
__device__ float g_xA[(size_t)D_IN * ROWS];     // x transposed: [k][row], row = t*32+b
__device__ float g_xg[(size_t)NCOL * ROWS];     // input projections, col-major: [col][row]
__device__ float g_hbuf[2][2][H_HID * BATCH];   // [buf][dir][k*32+b]
__device__ float g_part[128][T_LEN][BATCH];     // per-block logit partials
__device__ unsigned g_cnt[2];
__device__ unsigned g_gen[2];

// ---------------- f32x2 helpers ----------------
__device__ __forceinline__ unsigned long long splat2(float v) {
    unsigned long long r; unsigned u = __float_as_uint(v);
    asm("mov.b64 %0, {%1, %1};" : "=l"(r) : "r"(u));
    return r;
}
#define FMA2(acc, xv, wv) \
    asm("fma.rn.f32x2 %0, %1, %2, %0;" : "+l"(acc) : "l"(xv), "l"(wv))
__device__ __forceinline__ void unpack2(unsigned long long a, float& lo, float& hi) {
    unsigned l, h;
    asm("mov.b64 {%0, %1}, %2;" : "=r"(l), "=r"(h) : "l"(a));
    lo = __uint_as_float(l); hi = __uint_as_float(h);
}

// ---------------- per-direction grid barrier (atomic counter, proven R4) ----------------
__device__ __forceinline__ void bar_sync(int idx, unsigned count) {
    __syncthreads();
    if (threadIdx.x == 0) {
        __threadfence();
        unsigned gen = ((volatile unsigned*)g_gen)[idx];
        if (atomicAdd(&g_cnt[idx], 1u) == count - 1u) {
            g_cnt[idx] = 0;
            __threadfence();
            ((volatile unsigned*)g_gen)[idx] = gen + 1u;
        } else {
            while (((volatile unsigned*)g_gen)[idx] == gen) { }
        }
        __threadfence();
    }
    __syncthreads();
}

// ---------------- kernel 1: zero recurrent state ----------------
__global__ void zero_state_kernel() {
    int i = blockIdx.x * blockDim.x + threadIdx.x;
    ((float*)g_hbuf)[i] = 0.0f;       // 65536 threads exactly
}

// ---------------- kernel 2: transpose x[B][T][D] -> xA[k][t*32+b] ----------------
__global__ void transpose_x_kernel(const float* __restrict__ x) {
    __shared__ float tile[32][33];
    int t = blockIdx.x, k0 = blockIdx.y * 32, tid = threadIdx.x;
    int kk = tid & 31, r = tid >> 5;
#pragma unroll
    for (int i = 0; i < 4; ++i) {
        int b = r + i * 8;
        tile[kk][b] = x[((size_t)b * T_LEN + t) * D_IN + k0 + kk];
    }
    __syncthreads();
    int b2 = tid & 31, kr = tid >> 5;
#pragma unroll
    for (int i = 0; i < 4; ++i) {
        int kk2 = kr + i * 8;
        g_xA[(size_t)(k0 + kk2) * ROWS + t * 32 + b2] = tile[kk2][b2];
    }
}

// ---------------- kernel 3: xg = A @ [Wx_f | Wx_b]  (fp32 FFMA2 GEMM) ----------------
__global__ void __launch_bounds__(256, 2)
gemm_kernel(const float* __restrict__ Wx_f, const float* __restrict__ Wx_b) {
    extern __shared__ float sm[];
    float* xs  = sm;          // [2][32*128]  A tile  [kk][row]
    float* ws2 = sm + 8192;   // [2][32*128]  W tile, duplicated pairs [kk][col*2]

    const int tid = threadIdx.x;
    const int cb = blockIdx.x, rb = blockIdx.y;
    const int r = tid & 15, cg = tid >> 4;

    unsigned long long acc[4][4];
#pragma unroll
    for (int p = 0; p < 4; ++p)
#pragma unroll
        for (int c = 0; c < 4; ++c) acc[p][c] = 0ull;

    float4 ar[4], wr[2];

    auto load_regs = [&](int ti) {
        int k0 = ti * 32;
#pragma unroll
        for (int i = 0; i < 4; ++i) {
            int f = tid + i * 256;
            int kk = f >> 5, rc = (f & 31) * 4;
            ar[i] = *(const float4*)(g_xA + (size_t)(k0 + kk) * ROWS + rb * 128 + rc);
        }
#pragma unroll
        for (int i = 0; i < 2; ++i) {
            int f = tid + i * 256;
            int kk = f >> 4, cc = (f & 15) * 4;
            int gcol = cb * 64 + cc;
            const float* src = (gcol < G4)
                ? (Wx_f + (size_t)(k0 + kk) * G4 + gcol)
                : (Wx_b + (size_t)(k0 + kk) * G4 + (gcol - G4));
            wr[i] = *(const float4*)src;
        }
    };
    auto store_smem = [&](int buf) {
        float* xb = xs + buf * 4096;
        float* wb = ws2 + buf * 4096;
#pragma unroll
        for (int i = 0; i < 4; ++i) {
            int f = tid + i * 256;
            int kk = f >> 5, rc = (f & 31) * 4;
            *(float4*)(xb + kk * 128 + rc) = ar[i];
        }
#pragma unroll
        for (int i = 0; i < 2; ++i) {
            int f = tid + i * 256;
            int kk = f >> 4, cc = (f & 15) * 4;
            float4 w = wr[i];
            *(float4*)(wb + kk * 128 + cc * 2)     = make_float4(w.x, w.x, w.y, w.y);
            *(float4*)(wb + kk * 128 + cc * 2 + 4) = make_float4(w.z, w.z, w.w, w.w);
        }
    };

    load_regs(0);
    store_smem(0);
    __syncthreads();

    for (int ti = 0; ti < 32; ++ti) {
        if (ti + 1 < 32) load_regs(ti + 1);
        const float* xb = xs + (ti & 1) * 4096 + r * 8;
        const float* wb = ws2 + (ti & 1) * 4096 + cg * 8;
#pragma unroll 4
        for (int kk = 0; kk < 32; ++kk) {
            ulonglong2 xq0 = *(const ulonglong2*)(xb);
            ulonglong2 xq1 = *(const ulonglong2*)(xb + 4);
            ulonglong2 wq0 = *(const ulonglong2*)(wb);
            ulonglong2 wq1 = *(const ulonglong2*)(wb + 4);
            FMA2(acc[0][0], xq0.x, wq0.x); FMA2(acc[0][1], xq0.x, wq0.y);
            FMA2(acc[0][2], xq0.x, wq1.x); FMA2(acc[0][3], xq0.x, wq1.y);
            FMA2(acc[1][0], xq0.y, wq0.x); FMA2(acc[1][1], xq0.y, wq0.y);
            FMA2(acc[1][2], xq0.y, wq1.x); FMA2(acc[1][3], xq0.y, wq1.y);
            FMA2(acc[2][0], xq1.x, wq0.x); FMA2(acc[2][1], xq1.x, wq0.y);
            FMA2(acc[2][2], xq1.x, wq1.x); FMA2(acc[2][3], xq1.x, wq1.y);
            FMA2(acc[3][0], xq1.y, wq0.x); FMA2(acc[3][1], xq1.y, wq0.y);
            FMA2(acc[3][2], xq1.y, wq1.x); FMA2(acc[3][3], xq1.y, wq1.y);
            xb += 128; wb += 128;
        }
        if (ti + 1 < 32) store_smem((ti + 1) & 1);
        __syncthreads();
    }

#pragma unroll
    for (int c = 0; c < 4; ++c) {
        float v[8];
#pragma unroll
        for (int p = 0; p < 4; ++p) unpack2(acc[p][c], v[2 * p], v[2 * p + 1]);
        size_t col = (size_t)cb * 64 + cg * 4 + c;
        float* d = g_xg + col * ROWS + rb * 128 + r * 8;
        *(float4*)d       = make_float4(v[0], v[1], v[2], v[3]);
        *(float4*)(d + 4) = make_float4(v[4], v[5], v[6], v[7]);
    }
}

// ---------------- kernel 4: persistent recurrent phase ----------------
// 128 blocks, 256 threads. dir = blk>>6, 8 hidden units/block (j0=(blk&63)*8)
// = 32 gate columns. 16-way k-split, thread tile = 8 batch x 8 cols (32 FMA2/k).
__global__ void __launch_bounds__(256, 1)
lstm_kernel(const float* __restrict__ Wh_f, const float* __restrict__ Wh_b,
            const float* __restrict__ b_f,  const float* __restrict__ b_b,
            const float* __restrict__ Wfc)
{
    extern __shared__ float sm[];
    float* hs   = sm;             // 16384 fl (64KB) : h(t-1) [k][b]
    float* ws   = sm + 16384;     // 16384 fl (64KB) : Wh slice [k][cc]
    float* part = sm + 32768;     // 16384 fl (64KB) : [slice][cc][b]
    float* psum = sm + 49152;     // 256 fl

    const int tid = threadIdx.x;
    const int blk = blockIdx.x;
    const int dir = blk >> 6;
    const int j0  = (blk & 63) * 8;

    // k-loop mapping: 16 slices x 16 threads; tile = 8 b x 8 cols
    const int slice = tid >> 4;          // 0..15 (k range slice*32..+31)
    const int q     = tid & 15;
    const int bo    = q >> 2;            // batch octet: b = bo*8..+7
    const int cq    = q & 3;             // col octet:  cc = cq*8..+7

    // cell mapping
    const int u = tid >> 5;              // hidden unit 0..7
    const int b = tid & 31;              // batch

    const float* Wh   = dir ? Wh_b : Wh_f;
    const float* bias = dir ? b_b  : b_f;

    // load Wh slice once: ws[k*32 + cc] = Wh[k][(cc>>3)*512 + j0 + (cc&7)]
    for (int e = tid; e < 512 * 32; e += 256) {
        int k = e >> 5, cc = e & 31;
        ws[e] = Wh[(size_t)k * G4 + (cc >> 3) * 512 + j0 + (cc & 7)];
    }

    float biasr[4];
#pragma unroll
    for (int g = 0; g < 4; ++g) biasr[g] = bias[g * 512 + j0 + u];
    const float wfc = Wfc[dir * H_HID + j0 + u];

    float cstate = 0.0f;
    __syncthreads();

    for (int s = 0; s < T_LEN; ++s) {
        const int t = dir ? (T_LEN - 1 - s) : s;
        const float* hprev = g_hbuf[s & 1][dir];
        float*       hnext = g_hbuf[(s + 1) & 1][dir];

        // prefetch xg (independent of h)
        float xgv[4];
#pragma unroll
        for (int g = 0; g < 4; ++g)
            xgv[g] = __ldg(g_xg + (size_t)(dir * G4 + g * 512 + j0 + u) * ROWS + t * 32 + b);

        // stage h(t-1): 64KB, 16 float4/thread
        {
            const float4* src = (const float4*)hprev;
            float4* dst = (float4*)hs;
#pragma unroll
            for (int i = 0; i < 16; ++i) dst[tid + i * 256] = src[tid + i * 256];
        }
        __syncthreads();

        // k-loop: 32 k's; per k: 2 LDS.128 h + 2 LDS.128 w + 8 splat + 32 FMA2
        unsigned long long acc[8][4];
#pragma unroll
        for (int bi = 0; bi < 8; ++bi)
#pragma unroll
            for (int cp = 0; cp < 4; ++cp) acc[bi][cp] = 0ull;
        {
            const float* hp = hs + slice * 32 * 32 + bo * 8;
            const float* wp = ws + slice * 32 * 32 + cq * 8;
#pragma unroll 2
            for (int kk = 0; kk < 32; ++kk) {
                float4 h0 = *(const float4*)hp;
                float4 h1 = *(const float4*)(hp + 4);
                ulonglong2 wq0 = *(const ulonglong2*)wp;        // col pairs 0,1
                ulonglong2 wq1 = *(const ulonglong2*)(wp + 4);  // col pairs 2,3
                unsigned long long s0 = splat2(h0.x), s1 = splat2(h0.y);
                unsigned long long s2 = splat2(h0.z), s3 = splat2(h0.w);
                unsigned long long s4 = splat2(h1.x), s5 = splat2(h1.y);
                unsigned long long s6 = splat2(h1.z), s7 = splat2(h1.w);
                FMA2(acc[0][0], s0, wq0.x); FMA2(acc[0][1], s0, wq0.y);
                FMA2(acc[0][2], s0, wq1.x); FMA2(acc[0][3], s0, wq1.y);
                FMA2(acc[1][0], s1, wq0.x); FMA2(acc[1][1], s1, wq0.y);
                FMA2(acc[1][2], s1, wq1.x); FMA2(acc[1][3], s1, wq1.y);
                FMA2(acc[2][0], s2, wq0.x); FMA2(acc[2][1], s2, wq0.y);
                FMA2(acc[2][2], s2, wq1.x); FMA2(acc[2][3], s2, wq1.y);
                FMA2(acc[3][0], s3, wq0.x); FMA2(acc[3][1], s3, wq0.y);
                FMA2(acc[3][2], s3, wq1.x); FMA2(acc[3][3], s3, wq1.y);
                FMA2(acc[4][0], s4, wq0.x); FMA2(acc[4][1], s4, wq0.y);
                FMA2(acc[4][2], s4, wq1.x); FMA2(acc[4][3], s4, wq1.y);
                FMA2(acc[5][0], s5, wq0.x); FMA2(acc[5][1], s5, wq0.y);
                FMA2(acc[5][2], s5, wq1.x); FMA2(acc[5][3], s5, wq1.y);
                FMA2(acc[6][0], s6, wq0.x); FMA2(acc[6][1], s6, wq0.y);
                FMA2(acc[6][2], s6, wq1.x); FMA2(acc[6][3], s6, wq1.y);
                FMA2(acc[7][0], s7, wq0.x); FMA2(acc[7][1], s7, wq0.y);
                FMA2(acc[7][2], s7, wq1.x); FMA2(acc[7][3], s7, wq1.y);
                hp += 32; wp += 32;
            }
        }
        // write k-split partials: part[slice][cc][b], b fast
        {
            float* pb = part + slice * 1024 + bo * 8;
#pragma unroll
            for (int cp = 0; cp < 4; ++cp) {
                float* p0 = pb + (cq * 8 + 2 * cp) * 32;
#pragma unroll
                for (int bi = 0; bi < 8; ++bi) {
                    float lo, hi;
                    unpack2(acc[bi][cp], lo, hi);
                    p0[bi]      = lo;
                    p0[32 + bi] = hi;
                }
            }
        }
        __syncthreads();

        // epilogue: thread (u, b) computes cell update; conflict-free partial reads
        {
            float gate[4];
#pragma unroll
            for (int g = 0; g < 4; ++g) {
                float sum = xgv[g] + biasr[g];
                const float* pp = part + (g * 8 + u) * 32 + b;
#pragma unroll
                for (int sl = 0; sl < 16; ++sl) sum += pp[sl * 1024];
                gate[g] = sum;
            }
            float iv = 1.0f / (1.0f + __expf(-gate[0]));
            float fv = 1.0f / (1.0f + __expf(-gate[1]));
            float gv = tanhf(gate[2]);
            float ov = 1.0f / (1.0f + __expf(-gate[3]));
            cstate = fv * cstate + iv * gv;
            float hv = ov * tanhf(cstate);
            hnext[(j0 + u) * 32 + b] = hv;
            psum[tid] = hv * wfc;
        }
        __syncthreads();
        if (tid < 32) {
            float tot = 0.0f;
#pragma unroll
            for (int uu = 0; uu < 8; ++uu) tot += psum[tid + uu * 32];
            g_part[blk][t][tid] = tot;
        }
        if (s != T_LEN - 1) bar_sync(dir, 64);
    }
}

// ---------------- kernel 5: reduce partials + sigmoid ----------------
__global__ void finalize_kernel(const float* __restrict__ b_fc, float* __restrict__ out) {
    int g = blockIdx.x * blockDim.x + threadIdx.x;
    if (g >= T_LEN * BATCH) return;
    int t = g >> 5, b = g & 31;
    float acc = b_fc[0];
    const float* p = &g_part[0][t][b];
#pragma unroll 8
    for (int blk = 0; blk < 128; ++blk)
        acc += p[(size_t)blk * T_LEN * BATCH];
    out[(size_t)b * T_LEN + t] = 1.0f / (1.0f + __expf(-acc));
}

// ---------------- launcher ----------------
extern "C" void kernel_launch(void* const* d_in, const int* in_sizes, int n_in,
                              void* d_out, int out_size) {
    const float* x    = (const float*)d_in[0];
    const float* Wx_f = (const float*)d_in[1];
    const float* Wh_f = (const float*)d_in[2];
    const float* b_f  = (const float*)d_in[3];
    const float* Wx_b = (const float*)d_in[4];
    const float* Wh_b = (const float*)d_in[5];
    const float* b_b  = (const float*)d_in[6];
    const float* Wfc  = (const float*)d_in[7];
    const float* bfc  = (const float*)d_in[8];
    float* out = (float*)d_out;
    (void)in_sizes; (void)n_in; (void)out_size;

    cudaFuncSetAttribute(gemm_kernel, cudaFuncAttributeMaxDynamicSharedMemorySize, 65536);
    cudaFuncSetAttribute(lstm_kernel, cudaFuncAttributeMaxDynamicSharedMemorySize, 197632);

    zero_state_kernel<<<256, 256>>>();
    transpose_x_kernel<<<dim3(T_LEN, D_IN / 32), 256>>>(x);
    gemm_kernel<<<dim3(64, 256), 256, 65536>>>(Wx_f, Wx_b);
    lstm_kernel<<<128, 256, 197632>>>(Wh_f, Wh_b, b_f, b_b, Wfc);
    finalize_kernel<<<128, 256>>>(bfc, out);
}

// round 8
// speedup vs baseline: 1.4032x; 1.0336x over previous
#include <cuda_runtime.h>

#define T_LEN 1024
#define D_IN  1024
#define H_HID 512
#define G4    2048
#define BATCH 32
#define ROWS  32768          // T*B
#define NCOL  4096           // 2 dirs * 4H

// ---------------- device scratch ----------------
__device__ __align__(256) float g_xA[(size_t)D_IN * ROWS];   // x^T: [k][row]
__device__ __align__(256) float g_xg[(size_t)NCOL * ROWS];   // input proj, col-major
__device__ __align__(256) float g_hbuf[2][2][H_HID * BATCH]; // [buf][dir][k*32+b]
__device__ __align__(256) float g_part[128][T_LEN][BATCH];   // per-block logit partials
__device__ unsigned g_flag[2][64];   // per-block completed-step counters
__device__ unsigned g_gen2[2];       // per-dir published generation

// ---------------- f32x2 helpers ----------------
__device__ __forceinline__ unsigned long long splat2(float v) {
    unsigned long long r; unsigned u = __float_as_uint(v);
    asm("mov.b64 %0, {%1, %1};" : "=l"(r) : "r"(u));
    return r;
}
#define FMA2(acc, xv, wv) \
    asm("fma.rn.f32x2 %0, %1, %2, %0;" : "+l"(acc) : "l"(xv), "l"(wv))
__device__ __forceinline__ void unpack2(unsigned long long a, float& lo, float& hi) {
    unsigned l, h;
    asm("mov.b64 {%0, %1}, %2;" : "=r"(l), "=r"(h) : "l"(a));
    lo = __uint_as_float(l); hi = __uint_as_float(h);
}

// ---------------- acquire/release + mbarrier + bulk-copy helpers ----------------
__device__ __forceinline__ unsigned ld_acq(const unsigned* p) {
    unsigned v;
    asm volatile("ld.global.acquire.gpu.u32 %0, [%1];" : "=r"(v) : "l"(p) : "memory");
    return v;
}
__device__ __forceinline__ void st_rel(unsigned* p, unsigned v) {
    asm volatile("st.global.release.gpu.u32 [%0], %1;" :: "l"(p), "r"(v) : "memory");
}
__device__ __forceinline__ unsigned smem_u32(const void* p) {
    unsigned a;
    asm("{ .reg .u64 t; cvta.to.shared.u64 t, %1; cvt.u32.u64 %0, t; }" : "=r"(a) : "l"(p));
    return a;
}
__device__ __forceinline__ void mbar_init(unsigned mbar, unsigned count) {
    asm volatile("mbarrier.init.shared.b64 [%0], %1;" :: "r"(mbar), "r"(count) : "memory");
}
__device__ __forceinline__ void mbar_expect_tx(unsigned mbar, unsigned bytes) {
    asm volatile("mbarrier.arrive.expect_tx.shared.b64 _, [%0], %1;"
                 :: "r"(mbar), "r"(bytes) : "memory");
}
__device__ __forceinline__ void bulk_g2s(unsigned dst_smem, const void* src, unsigned bytes,
                                         unsigned mbar) {
    asm volatile(
        "cp.async.bulk.shared::cta.global.mbarrier::complete_tx::bytes [%0], [%1], %2, [%3];"
        :: "r"(dst_smem), "l"(src), "r"(bytes), "r"(mbar) : "memory");
}
__device__ __forceinline__ void mbar_wait(unsigned mbar, unsigned parity) {
    asm volatile(
        "{\n\t.reg .pred P;\n"
        "W%=:\n\t"
        "mbarrier.try_wait.parity.acquire.cta.shared::cta.b64 P, [%0], %1, 0x989680;\n\t"
        "@P bra D%=;\n\t"
        "bra W%=;\n"
        "D%=:\n\t}"
        :: "r"(mbar), "r"(parity) : "memory");
}

// ---------------- kernel 1: zero recurrent state + flags ----------------
__global__ void zero_state_kernel() {
    int i = blockIdx.x * blockDim.x + threadIdx.x;
    ((float*)g_hbuf)[i] = 0.0f;       // 65536 threads exactly
    if (i < 128) ((unsigned*)g_flag)[i] = 0u;
    if (i < 2)   g_gen2[i] = 0u;
}

// ---------------- kernel 2: transpose x[B][T][D] -> xA[k][t*32+b] ----------------
__global__ void transpose_x_kernel(const float* __restrict__ x) {
    __shared__ float tile[32][33];
    int t = blockIdx.x, k0 = blockIdx.y * 32, tid = threadIdx.x;
    int kk = tid & 31, r = tid >> 5;
#pragma unroll
    for (int i = 0; i < 4; ++i) {
        int b = r + i * 8;
        tile[kk][b] = x[((size_t)b * T_LEN + t) * D_IN + k0 + kk];
    }
    __syncthreads();
    int b2 = tid & 31, kr = tid >> 5;
#pragma unroll
    for (int i = 0; i < 4; ++i) {
        int kk2 = kr + i * 8;
        g_xA[(size_t)(k0 + kk2) * ROWS + t * 32 + b2] = tile[kk2][b2];
    }
}

// ---------------- kernel 3: xg = A @ [Wx_f | Wx_b]  (fp32 FFMA2 GEMM) ----------------
__global__ void __launch_bounds__(256, 2)
gemm_kernel(const float* __restrict__ Wx_f, const float* __restrict__ Wx_b) {
    extern __shared__ float sm[];
    float* xs  = sm;          // [2][32*128]  A tile  [kk][row]
    float* ws2 = sm + 8192;   // [2][32*128]  W tile, duplicated pairs [kk][col*2]

    const int tid = threadIdx.x;
    const int cb = blockIdx.x, rb = blockIdx.y;
    const int r = tid & 15, cg = tid >> 4;

    unsigned long long acc[4][4];
#pragma unroll
    for (int p = 0; p < 4; ++p)
#pragma unroll
        for (int c = 0; c < 4; ++c) acc[p][c] = 0ull;

    float4 ar[4], wr[2];

    auto load_regs = [&](int ti) {
        int k0 = ti * 32;
#pragma unroll
        for (int i = 0; i < 4; ++i) {
            int f = tid + i * 256;
            int kk = f >> 5, rc = (f & 31) * 4;
            ar[i] = *(const float4*)(g_xA + (size_t)(k0 + kk) * ROWS + rb * 128 + rc);
        }
#pragma unroll
        for (int i = 0; i < 2; ++i) {
            int f = tid + i * 256;
            int kk = f >> 4, cc = (f & 15) * 4;
            int gcol = cb * 64 + cc;
            const float* src = (gcol < G4)
                ? (Wx_f + (size_t)(k0 + kk) * G4 + gcol)
                : (Wx_b + (size_t)(k0 + kk) * G4 + (gcol - G4));
            wr[i] = *(const float4*)src;
        }
    };
    auto store_smem = [&](int buf) {
        float* xb = xs + buf * 4096;
        float* wb = ws2 + buf * 4096;
#pragma unroll
        for (int i = 0; i < 4; ++i) {
            int f = tid + i * 256;
            int kk = f >> 5, rc = (f & 31) * 4;
            *(float4*)(xb + kk * 128 + rc) = ar[i];
        }
#pragma unroll
        for (int i = 0; i < 2; ++i) {
            int f = tid + i * 256;
            int kk = f >> 4, cc = (f & 15) * 4;
            float4 w = wr[i];
            *(float4*)(wb + kk * 128 + cc * 2)     = make_float4(w.x, w.x, w.y, w.y);
            *(float4*)(wb + kk * 128 + cc * 2 + 4) = make_float4(w.z, w.z, w.w, w.w);
        }
    };

    load_regs(0);
    store_smem(0);
    __syncthreads();

    for (int ti = 0; ti < 32; ++ti) {
        if (ti + 1 < 32) load_regs(ti + 1);
        const float* xb = xs + (ti & 1) * 4096 + r * 8;
        const float* wb = ws2 + (ti & 1) * 4096 + cg * 8;
#pragma unroll 4
        for (int kk = 0; kk < 32; ++kk) {
            ulonglong2 xq0 = *(const ulonglong2*)(xb);
            ulonglong2 xq1 = *(const ulonglong2*)(xb + 4);
            ulonglong2 wq0 = *(const ulonglong2*)(wb);
            ulonglong2 wq1 = *(const ulonglong2*)(wb + 4);
            FMA2(acc[0][0], xq0.x, wq0.x); FMA2(acc[0][1], xq0.x, wq0.y);
            FMA2(acc[0][2], xq0.x, wq1.x); FMA2(acc[0][3], xq0.x, wq1.y);
            FMA2(acc[1][0], xq0.y, wq0.x); FMA2(acc[1][1], xq0.y, wq0.y);
            FMA2(acc[1][2], xq0.y, wq1.x); FMA2(acc[1][3], xq0.y, wq1.y);
            FMA2(acc[2][0], xq1.x, wq0.x); FMA2(acc[2][1], xq1.x, wq0.y);
            FMA2(acc[2][2], xq1.x, wq1.x); FMA2(acc[2][3], xq1.x, wq1.y);
            FMA2(acc[3][0], xq1.y, wq0.x); FMA2(acc[3][1], xq1.y, wq0.y);
            FMA2(acc[3][2], xq1.y, wq1.x); FMA2(acc[3][3], xq1.y, wq1.y);
            xb += 128; wb += 128;
        }
        if (ti + 1 < 32) store_smem((ti + 1) & 1);
        __syncthreads();
    }

#pragma unroll
    for (int c = 0; c < 4; ++c) {
        float v[8];
#pragma unroll
        for (int p = 0; p < 4; ++p) unpack2(acc[p][c], v[2 * p], v[2 * p + 1]);
        size_t col = (size_t)cb * 64 + cg * 4 + c;
        float* d = g_xg + col * ROWS + rb * 128 + r * 8;
        *(float4*)d       = make_float4(v[0], v[1], v[2], v[3]);
        *(float4*)(d + 4) = make_float4(v[4], v[5], v[6], v[7]);
    }
}

// ---------------- kernel 4: persistent recurrent phase ----------------
// 128 blocks, 256 threads. dir = blk>>6, 8 hidden units/block (j0=(blk&63)*8)
// = 32 gate columns. 16-way k-split, thread tile = 8 batch x 8 cols (32 FMA2/k).
// h staged via cp.async.bulk; barrier = per-block release flags + 1 checker/dir.
__global__ void __launch_bounds__(256, 1)
lstm_kernel(const float* __restrict__ Wh_f, const float* __restrict__ Wh_b,
            const float* __restrict__ b_f,  const float* __restrict__ b_b,
            const float* __restrict__ Wfc)
{
    extern __shared__ float sm[];
    float* hs   = sm;             // 16384 fl (64KB) : h(t-1) [k][b]
    float* ws   = sm + 16384;     // 16384 fl (64KB) : Wh slice [k][cc]
    float* part = sm + 32768;     // 16384 fl (64KB) : [slice][cc][b]
    float* psum = sm + 49152;     // 256 fl
    unsigned long long* mbar_p = (unsigned long long*)(sm + 49408);

    const int tid = threadIdx.x;
    const int blk = blockIdx.x;
    const int dir = blk >> 6;
    const int j0  = (blk & 63) * 8;
    const bool checker = ((blk & 63) == 0);

    // k-loop mapping: 16 slices x 16 threads; tile = 8 b x 8 cols
    const int slice = tid >> 4;          // 0..15 (k range slice*32..+31)
    const int q     = tid & 15;
    const int bo    = q >> 2;            // batch octet
    const int cq    = q & 3;             // col octet

    // cell mapping
    const int u = tid >> 5;              // hidden unit 0..7
    const int b = tid & 31;              // batch

    const float* Wh   = dir ? Wh_b : Wh_f;
    const float* bias = dir ? b_b  : b_f;

    const unsigned mbar = smem_u32(mbar_p);
    const unsigned hs_u = smem_u32(hs);
    if (tid == 0) mbar_init(mbar, 1);

    // load Wh slice once: ws[k*32 + cc] = Wh[k][(cc>>3)*512 + j0 + (cc&7)]
    for (int e = tid; e < 512 * 32; e += 256) {
        int k = e >> 5, cc = e & 31;
        ws[e] = Wh[(size_t)k * G4 + (cc >> 3) * 512 + j0 + (cc & 7)];
    }

    float biasr[4];
#pragma unroll
    for (int g = 0; g < 4; ++g) biasr[g] = bias[g * 512 + j0 + u];
    const float wfc = Wfc[dir * H_HID + j0 + u];

    float cstate = 0.0f;
    __syncthreads();

    for (int s = 0; s < T_LEN; ++s) {
        const int t = dir ? (T_LEN - 1 - s) : s;
        const float* hprev = g_hbuf[s & 1][dir];
        float*       hnext = g_hbuf[(s + 1) & 1][dir];

        // prefetch xg (independent of h)
        float xgv[4];
#pragma unroll
        for (int g = 0; g < 4; ++g)
            xgv[g] = __ldg(g_xg + (size_t)(dir * G4 + g * 512 + j0 + u) * ROWS + t * 32 + b);

        // inter-block sync: flags -> checker -> gen
        if (s > 0) {
            if (checker) {
                if (tid < 32) {
                    const unsigned* fa = &g_flag[dir][tid];
                    const unsigned* fb = &g_flag[dir][tid + 32];
                    bool ok;
                    do {
                        ok = (ld_acq(fa) >= (unsigned)s) && (ld_acq(fb) >= (unsigned)s);
                    } while (!__all_sync(0xffffffffu, ok));
                    if (tid == 0) st_rel(&g_gen2[dir], (unsigned)s);
                }
            } else {
                if (tid == 0) {
                    while (ld_acq(&g_gen2[dir]) < (unsigned)s) { }
                }
            }
        }
        // async stage h(t-1): 64KB in one bulk copy
        if (tid == 0) {
            mbar_expect_tx(mbar, 65536u);
            bulk_g2s(hs_u, hprev, 65536u, mbar);
        }
        mbar_wait(mbar, s & 1);

        // k-loop: 32 k's; per k: 2 LDS.128 h + 2 LDS.128 w + 8 splat + 32 FMA2
        unsigned long long acc[8][4];
#pragma unroll
        for (int bi = 0; bi < 8; ++bi)
#pragma unroll
            for (int cp = 0; cp < 4; ++cp) acc[bi][cp] = 0ull;
        {
            const float* hp = hs + slice * 32 * 32 + bo * 8;
            const float* wp = ws + slice * 32 * 32 + cq * 8;
#pragma unroll 2
            for (int kk = 0; kk < 32; ++kk) {
                float4 h0 = *(const float4*)hp;
                float4 h1 = *(const float4*)(hp + 4);
                ulonglong2 wq0 = *(const ulonglong2*)wp;
                ulonglong2 wq1 = *(const ulonglong2*)(wp + 4);
                unsigned long long s0 = splat2(h0.x), s1 = splat2(h0.y);
                unsigned long long s2 = splat2(h0.z), s3 = splat2(h0.w);
                unsigned long long s4 = splat2(h1.x), s5 = splat2(h1.y);
                unsigned long long s6 = splat2(h1.z), s7 = splat2(h1.w);
                FMA2(acc[0][0], s0, wq0.x); FMA2(acc[0][1], s0, wq0.y);
                FMA2(acc[0][2], s0, wq1.x); FMA2(acc[0][3], s0, wq1.y);
                FMA2(acc[1][0], s1, wq0.x); FMA2(acc[1][1], s1, wq0.y);
                FMA2(acc[1][2], s1, wq1.x); FMA2(acc[1][3], s1, wq1.y);
                FMA2(acc[2][0], s2, wq0.x); FMA2(acc[2][1], s2, wq0.y);
                FMA2(acc[2][2], s2, wq1.x); FMA2(acc[2][3], s2, wq1.y);
                FMA2(acc[3][0], s3, wq0.x); FMA2(acc[3][1], s3, wq0.y);
                FMA2(acc[3][2], s3, wq1.x); FMA2(acc[3][3], s3, wq1.y);
                FMA2(acc[4][0], s4, wq0.x); FMA2(acc[4][1], s4, wq0.y);
                FMA2(acc[4][2], s4, wq1.x); FMA2(acc[4][3], s4, wq1.y);
                FMA2(acc[5][0], s5, wq0.x); FMA2(acc[5][1], s5, wq0.y);
                FMA2(acc[5][2], s5, wq1.x); FMA2(acc[5][3], s5, wq1.y);
                FMA2(acc[6][0], s6, wq0.x); FMA2(acc[6][1], s6, wq0.y);
                FMA2(acc[6][2], s6, wq1.x); FMA2(acc[6][3], s6, wq1.y);
                FMA2(acc[7][0], s7, wq0.x); FMA2(acc[7][1], s7, wq0.y);
                FMA2(acc[7][2], s7, wq1.x); FMA2(acc[7][3], s7, wq1.y);
                hp += 32; wp += 32;
            }
        }
        // write k-split partials: part[slice][cc][b]
        {
            float* pb = part + slice * 1024 + bo * 8;
#pragma unroll
            for (int cp = 0; cp < 4; ++cp) {
                float* p0 = pb + (cq * 8 + 2 * cp) * 32;
#pragma unroll
                for (int bi = 0; bi < 8; ++bi) {
                    float lo, hi;
                    unpack2(acc[bi][cp], lo, hi);
                    p0[bi]      = lo;
                    p0[32 + bi] = hi;
                }
            }
        }
        __syncthreads();

        // epilogue: thread (u, b) computes cell update
        {
            float gate[4];
#pragma unroll
            for (int g = 0; g < 4; ++g) {
                float sum = xgv[g] + biasr[g];
                const float* pp = part + (g * 8 + u) * 32 + b;
#pragma unroll
                for (int sl = 0; sl < 16; ++sl) sum += pp[sl * 1024];
                gate[g] = sum;
            }
            float iv = 1.0f / (1.0f + __expf(-gate[0]));
            float fv = 1.0f / (1.0f + __expf(-gate[1]));
            float gv = tanhf(gate[2]);
            float ov = 1.0f / (1.0f + __expf(-gate[3]));
            cstate = fv * cstate + iv * gv;
            float hv = ov * tanhf(cstate);
            hnext[(j0 + u) * 32 + b] = hv;
            psum[tid] = hv * wfc;
        }
        __syncthreads();
        // publish step completion (release covers hnext writes via syncthreads hb)
        if (tid == 64 && s + 1 < T_LEN)
            st_rel(&g_flag[dir][blk & 63], (unsigned)(s + 1));
        if (tid < 32) {
            float tot = 0.0f;
#pragma unroll
            for (int uu = 0; uu < 8; ++uu) tot += psum[tid + uu * 32];
            g_part[blk][t][tid] = tot;
        }
    }
}

// ---------------- kernel 5: reduce partials + sigmoid ----------------
__global__ void finalize_kernel(const float* __restrict__ b_fc, float* __restrict__ out) {
    int g = blockIdx.x * blockDim.x + threadIdx.x;
    if (g >= T_LEN * BATCH) return;
    int t = g >> 5, b = g & 31;
    float acc = b_fc[0];
    const float* p = &g_part[0][t][b];
#pragma unroll 8
    for (int blk = 0; blk < 128; ++blk)
        acc += p[(size_t)blk * T_LEN * BATCH];
    out[(size_t)b * T_LEN + t] = 1.0f / (1.0f + __expf(-acc));
}

// ---------------- launcher ----------------
extern "C" void kernel_launch(void* const* d_in, const int* in_sizes, int n_in,
                              void* d_out, int out_size) {
    const float* x    = (const float*)d_in[0];
    const float* Wx_f = (const float*)d_in[1];
    const float* Wh_f = (const float*)d_in[2];
    const float* b_f  = (const float*)d_in[3];
    const float* Wx_b = (const float*)d_in[4];
    const float* Wh_b = (const float*)d_in[5];
    const float* b_b  = (const float*)d_in[6];
    const float* Wfc  = (const float*)d_in[7];
    const float* bfc  = (const float*)d_in[8];
    float* out = (float*)d_out;
    (void)in_sizes; (void)n_in; (void)out_size;

    cudaFuncSetAttribute(gemm_kernel, cudaFuncAttributeMaxDynamicSharedMemorySize, 65536);
    cudaFuncSetAttribute(lstm_kernel, cudaFuncAttributeMaxDynamicSharedMemorySize, 197664);

    zero_state_kernel<<<256, 256>>>();
    transpose_x_kernel<<<dim3(T_LEN, D_IN / 32), 256>>>(x);
    gemm_kernel<<<dim3(64, 256), 256, 65536>>>(Wx_f, Wx_b);
    lstm_kernel<<<128, 256, 197664>>>(Wh_f, Wh_b, b_f, b_b, Wfc);
    finalize_kernel<<<128, 256>>>(bfc, out);
}